// round 1
// baseline (speedup 1.0000x reference)
#include <cuda_runtime.h>
#include <cstdint>

#define IMGS 8
#define HH 1024
#define WPX 1024
#define WW 32            // 32-bit words per row
#define MAXIT 64

// Static scratch (no allocations allowed)
__device__ uint32_t g_buf[2][IMGS][HH][WW];   // ping-pong bitpacked images (2 MB)
__device__ uint32_t g_cbits[IMGS][HH][WW];    // endpoint bits (1 MB)
__device__ int      g_flag[IMGS * MAXIT];     // per-image per-iteration changed flags
__device__ double   g_partial[1024];          // block partial sums

// ---------------------------------------------------------------------------
// helpers
// ---------------------------------------------------------------------------
__device__ __forceinline__ uint32_t shW(uint32_t l, uint32_t m) {
    // west neighbor mask: bit k = pixel at column-1  => (m<<1)|(l>>31)
    return __funnelshift_l(l, m, 1);
}
__device__ __forceinline__ uint32_t shE(uint32_t m, uint32_t r) {
    // east neighbor mask: bit k = pixel at column+1  => (m>>1)|(r<<31)
    return __funnelshift_r(m, r, 1);
}

struct Bn4 { uint32_t n0, n1, n2, n3; };  // bit-sliced neighbor count (weights 1,2,4,8)

__device__ __forceinline__ Bn4 bn8(uint32_t P2, uint32_t P3, uint32_t P4, uint32_t P5,
                                   uint32_t P6, uint32_t P7, uint32_t P8, uint32_t P9) {
    uint32_t s1 = P2 ^ P3 ^ P4, k1 = (P2 & P3) | (P4 & (P2 | P3));
    uint32_t s2 = P5 ^ P6 ^ P7, k2 = (P5 & P6) | (P7 & (P5 | P6));
    uint32_t s3 = s1 ^ s2 ^ P8, k3 = (s1 & s2) | (P8 & (s1 | s2));
    uint32_t n0 = s3 ^ P9,      k4 = s3 & P9;
    uint32_t s4 = k1 ^ k2 ^ k3, k5 = (k1 & k2) | (k3 & (k1 | k2));
    uint32_t n1 = s4 ^ k4,      k6 = s4 & k4;
    Bn4 r; r.n0 = n0; r.n1 = n1; r.n2 = k5 ^ k6; r.n3 = k5 & k6; return r;
}

// ---------------------------------------------------------------------------
// K1: threshold + bitpack pred>=0.5 into g_buf[0]; zero flags
// ---------------------------------------------------------------------------
__global__ void __launch_bounds__(256) k_pack(const float* __restrict__ pred) {
    int warp = threadIdx.x >> 5, lane = threadIdx.x & 31;
    int ry = blockIdx.x * 8 + warp;            // global row 0..8191
    int img = ry >> 10, y = ry & 1023;
    const float* row = pred + (size_t)ry * WPX;
    #pragma unroll 4
    for (int w = 0; w < WW; ++w) {
        float p = row[w * 32 + lane];
        unsigned b = __ballot_sync(0xffffffffu, p >= 0.5f);
        if (lane == 0) g_buf[0][img][y][w] = b;
    }
    if (blockIdx.x == 0 && threadIdx.x < IMGS * MAXIT) g_flag[threadIdx.x] = 0;
}

// ---------------------------------------------------------------------------
// K2: persistent cluster thinning. One 8-CTA cluster per image.
// ---------------------------------------------------------------------------
__device__ __forceinline__ void cluster_sync_() {
    asm volatile("barrier.cluster.arrive.aligned;" ::: "memory");
    asm volatile("barrier.cluster.wait.aligned;" ::: "memory");
}

template <int SUB>
__device__ __forceinline__ uint32_t thin_words(const uint32_t* __restrict__ S,
                                               uint32_t* __restrict__ D,
                                               int y, int w0) {
    uint32_t a[10], c[10], b[10];
    const uint32_t* rc = S + y * WW;
    bool yt = (y == 0), yb = (y == HH - 1);
    #pragma unroll
    for (int i = 0; i < 10; ++i) {
        int w = w0 - 1 + i;
        bool ok = (w >= 0) && (w < WW);
        c[i] = ok ? rc[w] : 0u;
        a[i] = (ok && !yt) ? rc[w - WW] : 0u;
        b[i] = (ok && !yb) ? rc[w + WW] : 0u;
    }
    uint32_t ch = 0;
    #pragma unroll
    for (int i = 0; i < 8; ++i) {
        uint32_t aL = a[i], aM = a[i + 1], aR = a[i + 2];
        uint32_t cL = c[i], cM = c[i + 1], cR = c[i + 2];
        uint32_t bL = b[i], bM = b[i + 1], bR = b[i + 2];
        uint32_t P2 = aM, P6 = bM;
        uint32_t P3 = shE(aM, aR), P4 = shE(cM, cR), P5 = shE(bM, bR);
        uint32_t P7 = shW(bL, bM), P8 = shW(cL, cM), P9 = shW(aL, aM);
        Bn4 n = bn8(P2, P3, P4, P5, P6, P7, P8, P9);
        uint32_t ge2 = n.n1 | n.n2 | n.n3;
        uint32_t ge7 = n.n3 | (n.n0 & n.n1 & n.n2);
        uint32_t condB = ge2 & ~ge7;
        // exactly-one 0->1 transition around P2..P9..P2
        uint32_t t, acc, multi;
        acc = ~P2 & P3; multi = 0u;
        t = ~P3 & P4; multi |= acc & t; acc |= t;
        t = ~P4 & P5; multi |= acc & t; acc |= t;
        t = ~P5 & P6; multi |= acc & t; acc |= t;
        t = ~P6 & P7; multi |= acc & t; acc |= t;
        t = ~P7 & P8; multi |= acc & t; acc |= t;
        t = ~P8 & P9; multi |= acc & t; acc |= t;
        t = ~P9 & P2; multi |= acc & t; acc |= t;
        uint32_t A1 = acc & ~multi;
        uint32_t e1, e2;
        if (SUB == 0) { e1 = ~(P2 & P4 & P6); e2 = ~(P4 & P6 & P8); }
        else          { e1 = ~(P2 & P4 & P8); e2 = ~(P2 & P6 & P8); }
        uint32_t rem = cM & condB & A1 & e1 & e2;
        D[y * WW + w0 + i] = cM ^ rem;    // rem subset of cM
        ch |= rem;
    }
    return ch;
}

__global__ void __cluster_dims__(8, 1, 1) __launch_bounds__(512, 1) k_thin() {
    int img  = blockIdx.x >> 3;
    int rank = blockIdx.x & 7;
    int tid  = threadIdx.x;
    int y    = rank * 128 + (tid >> 2);
    int w0   = (tid & 3) * 8;
    uint32_t* B0 = &g_buf[0][img][0][0];
    uint32_t* B1 = &g_buf[1][img][0][0];
    int* flag = &g_flag[img * MAXIT];
    __shared__ int sflag;

    for (int iter = 0; iter < MAXIT; ++iter) {
        if (tid == 0) sflag = 0;
        __syncthreads();
        uint32_t ch = thin_words<0>(B0, B1, y, w0);
        if (__any_sync(0xffffffffu, ch != 0u) && (tid & 31) == 0) sflag = 1;
        __threadfence();
        cluster_sync_();                      // B1 complete, visible cluster-wide
        ch = thin_words<1>(B1, B0, y, w0);
        if (__any_sync(0xffffffffu, ch != 0u) && (tid & 31) == 0) sflag = 1;
        __syncthreads();
        if (tid == 0 && sflag) atomicOr(&flag[iter], 1);
        __threadfence();
        cluster_sync_();                      // B0 complete + flags visible
        if (__ldcg(&flag[iter]) == 0) break;  // uniform across the cluster
    }
}

// ---------------------------------------------------------------------------
// K3: endpoint bits  C = skeleton & (neighbor count == 1)
// ---------------------------------------------------------------------------
__global__ void __launch_bounds__(256) k_endpoint() {
    int idx = blockIdx.x * 256 + threadIdx.x;   // 0..262143
    int w = idx & 31, y = (idx >> 5) & 1023, img = idx >> 15;
    const uint32_t* S = &g_buf[0][img][0][0];
    uint32_t aL = 0, aM = 0, aR = 0, bL = 0, bM = 0, bR = 0;
    uint32_t cL = (w > 0) ? S[y * WW + w - 1] : 0u;
    uint32_t cM = S[y * WW + w];
    uint32_t cR = (w < WW - 1) ? S[y * WW + w + 1] : 0u;
    if (y > 0) {
        aM = S[(y - 1) * WW + w];
        aL = (w > 0) ? S[(y - 1) * WW + w - 1] : 0u;
        aR = (w < WW - 1) ? S[(y - 1) * WW + w + 1] : 0u;
    }
    if (y < HH - 1) {
        bM = S[(y + 1) * WW + w];
        bL = (w > 0) ? S[(y + 1) * WW + w - 1] : 0u;
        bR = (w < WW - 1) ? S[(y + 1) * WW + w + 1] : 0u;
    }
    uint32_t P2 = aM, P6 = bM;
    uint32_t P3 = shE(aM, aR), P4 = shE(cM, cR), P5 = shE(bM, bR);
    uint32_t P7 = shW(bL, bM), P8 = shW(cL, cM), P9 = shW(aL, aM);
    Bn4 n = bn8(P2, P3, P4, P5, P6, P7, P8, P9);
    uint32_t C = cM & n.n0 & ~(n.n1 | n.n2 | n.n3);
    g_cbits[img][y][w] = C;
}

// ---------------------------------------------------------------------------
// K4: fused 9x9 endpoint-density weight + BCE, block partial sums (double)
// ---------------------------------------------------------------------------
__global__ void __launch_bounds__(256) k_loss(const float* __restrict__ pred,
                                              const float* __restrict__ targ) {
    int idx = blockIdx.x * 256 + threadIdx.x;   // thread per 32-px word
    int w = idx & 31, y = (idx >> 5) & 1023, img = idx >> 15;
    const uint32_t* C = &g_cbits[img][0][0];

    uint32_t vlo[9], vhi[9], orAll = 0;
    #pragma unroll
    for (int d = 0; d < 9; ++d) {
        int r = y + d - 4;
        uint32_t L = 0, M = 0, R = 0;
        if (r >= 0 && r < HH) {
            M = C[r * WW + w];
            L = (w > 0) ? C[r * WW + w - 1] : 0u;
            R = (w < WW - 1) ? C[r * WW + w + 1] : 0u;
        }
        // 40-bit window: bit (c+4) <-> column 32*w + c, c in [-4, 35]
        vlo[d] = (L >> 28) | (M << 4);
        vhi[d] = (M >> 28) | ((R & 0xFu) << 4);
        orAll |= vlo[d] | vhi[d];
    }

    size_t poff = ((size_t)img * HH + y) * WPX + (size_t)w * 32;
    const float4* p4 = (const float4*)(pred + poff);
    const float4* t4 = (const float4*)(targ + poff);
    double lsum = 0.0;
    #pragma unroll
    for (int q = 0; q < 8; ++q) {
        float4 pv = p4[q], tv = t4[q];
        float pa[4] = {pv.x, pv.y, pv.z, pv.w};
        float ta[4] = {tv.x, tv.y, tv.z, tv.w};
        #pragma unroll
        for (int j = 0; j < 4; ++j) {
            int k = q * 4 + j;
            float p = pa[j], t = ta[j];
            float Lb = -(t * __logf(p) + (1.0f - t) * __logf(1.0f - p));
            float Wt = 1.0f;
            if (orAll) {
                int nsum = 0;
                #pragma unroll
                for (int d = 0; d < 9; ++d)
                    nsum += __popc(__funnelshift_r(vlo[d], vhi[d], k) & 0x1FFu);
                if (nsum) Wt = 60.0f * (float)nsum;
            }
            lsum += (double)(Wt * Lb);
        }
    }
    __shared__ double sd[256];
    sd[threadIdx.x] = lsum;
    __syncthreads();
    #pragma unroll
    for (int s = 128; s > 0; s >>= 1) {
        if (threadIdx.x < s) sd[threadIdx.x] += sd[threadIdx.x + s];
        __syncthreads();
    }
    if (threadIdx.x == 0) g_partial[blockIdx.x] = sd[0];
}

// ---------------------------------------------------------------------------
// K5: deterministic final reduction -> mean (float)
// ---------------------------------------------------------------------------
__global__ void __launch_bounds__(1024) k_reduce(float* __restrict__ out) {
    __shared__ double sd[1024];
    int t = threadIdx.x;
    sd[t] = g_partial[t];
    __syncthreads();
    #pragma unroll
    for (int s = 512; s > 0; s >>= 1) {
        if (t < s) sd[t] += sd[t + s];
        __syncthreads();
    }
    if (t == 0) out[0] = (float)(sd[0] * (1.0 / ((double)IMGS * HH * WPX)));
}

// ---------------------------------------------------------------------------
extern "C" void kernel_launch(void* const* d_in, const int* in_sizes, int n_in,
                              void* d_out, int out_size) {
    (void)in_sizes; (void)n_in; (void)out_size;
    const float* pred = (const float*)d_in[0];
    const float* targ = (const float*)d_in[1];
    float* out = (float*)d_out;

    k_pack<<<1024, 256>>>(pred);
    k_thin<<<64, 512>>>();
    k_endpoint<<<1024, 256>>>();
    k_loss<<<1024, 256>>>(pred, targ);
    k_reduce<<<1, 1024>>>(out);
}

// round 2
// speedup vs baseline: 1.2420x; 1.2420x over previous
#include <cuda_runtime.h>
#include <cstdint>

#define IMGS 8
#define HH 1024
#define WPX 1024
#define WW 32            // 32-bit words per row
#define MAXIT 64

// Static scratch (no allocations allowed)
__device__ uint32_t g_buf[2][IMGS][HH][WW];   // ping-pong bitpacked images (2 MB)
__device__ uint32_t g_cbits[IMGS][HH][WW];    // endpoint bits (1 MB)
__device__ int      g_flag[IMGS * MAXIT];     // per-image per-iteration changed flags
__device__ uint8_t  g_rowch[3][IMGS][HH];     // rolling per-row change flags
__device__ double   g_partial[1024];          // block partial sums

// ---------------------------------------------------------------------------
// helpers
// ---------------------------------------------------------------------------
__device__ __forceinline__ uint32_t shW(uint32_t l, uint32_t m) {
    return __funnelshift_l(l, m, 1);     // west neighbor mask
}
__device__ __forceinline__ uint32_t shE(uint32_t m, uint32_t r) {
    return __funnelshift_r(m, r, 1);     // east neighbor mask
}

struct Bn4 { uint32_t n0, n1, n2, n3; };  // bit-sliced neighbor count

__device__ __forceinline__ Bn4 bn8(uint32_t P2, uint32_t P3, uint32_t P4, uint32_t P5,
                                   uint32_t P6, uint32_t P7, uint32_t P8, uint32_t P9) {
    uint32_t s1 = P2 ^ P3 ^ P4, k1 = (P2 & P3) | (P4 & (P2 | P3));
    uint32_t s2 = P5 ^ P6 ^ P7, k2 = (P5 & P6) | (P7 & (P5 | P6));
    uint32_t s3 = s1 ^ s2 ^ P8, k3 = (s1 & s2) | (P8 & (s1 | s2));
    uint32_t n0 = s3 ^ P9,      k4 = s3 & P9;
    uint32_t s4 = k1 ^ k2 ^ k3, k5 = (k1 & k2) | (k3 & (k1 | k2));
    uint32_t n1 = s4 ^ k4,      k6 = s4 & k4;
    Bn4 r; r.n0 = n0; r.n1 = n1; r.n2 = k5 ^ k6; r.n3 = k5 & k6; return r;
}

// ---------------------------------------------------------------------------
// K1: threshold + bitpack pred>=0.5 into g_buf[0]; zero iteration flags
// ---------------------------------------------------------------------------
__global__ void __launch_bounds__(256) k_pack(const float* __restrict__ pred) {
    int warp = threadIdx.x >> 5, lane = threadIdx.x & 31;
    int ry = blockIdx.x * 8 + warp;            // global row 0..8191
    int img = ry >> 10, y = ry & 1023;
    const float* row = pred + (size_t)ry * WPX;
    #pragma unroll 4
    for (int w = 0; w < WW; ++w) {
        float p = row[w * 32 + lane];
        unsigned b = __ballot_sync(0xffffffffu, p >= 0.5f);
        if (lane == 0) g_buf[0][img][y][w] = b;
    }
    int z = blockIdx.x * 256 + threadIdx.x;
    if (z < IMGS * MAXIT) g_flag[z] = 0;
}

// ---------------------------------------------------------------------------
// K2: persistent cluster thinning (8 CTAs/image) with dirty-row skipping,
//     endpoint extraction fused at the end.
// ---------------------------------------------------------------------------
__device__ __forceinline__ void cluster_sync_() {
    asm volatile("barrier.cluster.arrive.aligned;" ::: "memory");
    asm volatile("barrier.cluster.wait.aligned;" ::: "memory");
}

template <int SUB>
__device__ __forceinline__ uint32_t thin_words(const uint32_t* __restrict__ S,
                                               uint32_t* __restrict__ D,
                                               int y, int w0) {
    uint32_t a[10], c[10], b[10];
    const uint32_t* rc = S + y * WW;
    bool yt = (y == 0), yb = (y == HH - 1);
    #pragma unroll
    for (int i = 0; i < 10; ++i) {
        int w = w0 - 1 + i;
        bool ok = (w >= 0) && (w < WW);
        c[i] = ok ? rc[w] : 0u;
        a[i] = (ok && !yt) ? rc[w - WW] : 0u;
        b[i] = (ok && !yb) ? rc[w + WW] : 0u;
    }
    uint32_t ch = 0;
    #pragma unroll
    for (int i = 0; i < 8; ++i) {
        uint32_t aL = a[i], aM = a[i + 1], aR = a[i + 2];
        uint32_t cL = c[i], cM = c[i + 1], cR = c[i + 2];
        uint32_t bL = b[i], bM = b[i + 1], bR = b[i + 2];
        uint32_t P2 = aM, P6 = bM;
        uint32_t P3 = shE(aM, aR), P4 = shE(cM, cR), P5 = shE(bM, bR);
        uint32_t P7 = shW(bL, bM), P8 = shW(cL, cM), P9 = shW(aL, aM);
        Bn4 n = bn8(P2, P3, P4, P5, P6, P7, P8, P9);
        uint32_t ge2 = n.n1 | n.n2 | n.n3;
        uint32_t ge7 = n.n3 | (n.n0 & n.n1 & n.n2);
        uint32_t condB = ge2 & ~ge7;
        uint32_t t, acc, multi;
        acc = ~P2 & P3; multi = 0u;
        t = ~P3 & P4; multi |= acc & t; acc |= t;
        t = ~P4 & P5; multi |= acc & t; acc |= t;
        t = ~P5 & P6; multi |= acc & t; acc |= t;
        t = ~P6 & P7; multi |= acc & t; acc |= t;
        t = ~P7 & P8; multi |= acc & t; acc |= t;
        t = ~P8 & P9; multi |= acc & t; acc |= t;
        t = ~P9 & P2; multi |= acc & t; acc |= t;
        uint32_t A1 = acc & ~multi;
        uint32_t e1, e2;
        if (SUB == 0) { e1 = ~(P2 & P4 & P6); e2 = ~(P4 & P6 & P8); }
        else          { e1 = ~(P2 & P4 & P8); e2 = ~(P2 & P6 & P8); }
        uint32_t rem = cM & condB & A1 & e1 & e2;
        D[y * WW + w0 + i] = cM ^ rem;
        ch |= rem;
    }
    return ch;
}

__device__ __forceinline__ void endpoint_words(const uint32_t* __restrict__ S,
                                               int img, int y, int w0) {
    uint32_t a[10], c[10], b[10];
    const uint32_t* rc = S + y * WW;
    bool yt = (y == 0), yb = (y == HH - 1);
    #pragma unroll
    for (int i = 0; i < 10; ++i) {
        int w = w0 - 1 + i;
        bool ok = (w >= 0) && (w < WW);
        c[i] = ok ? rc[w] : 0u;
        a[i] = (ok && !yt) ? rc[w - WW] : 0u;
        b[i] = (ok && !yb) ? rc[w + WW] : 0u;
    }
    #pragma unroll
    for (int i = 0; i < 8; ++i) {
        uint32_t aL = a[i], aM = a[i + 1], aR = a[i + 2];
        uint32_t cL = c[i], cM = c[i + 1], cR = c[i + 2];
        uint32_t bL = b[i], bM = b[i + 1], bR = b[i + 2];
        uint32_t P2 = aM, P6 = bM;
        uint32_t P3 = shE(aM, aR), P4 = shE(cM, cR), P5 = shE(bM, bR);
        uint32_t P7 = shW(bL, bM), P8 = shW(cL, cM), P9 = shW(aL, aM);
        Bn4 n = bn8(P2, P3, P4, P5, P6, P7, P8, P9);
        g_cbits[img][y][w0 + i] = cM & n.n0 & ~(n.n1 | n.n2 | n.n3);
    }
}

__global__ void __cluster_dims__(8, 1, 1) __launch_bounds__(512, 1) k_thin() {
    int img  = blockIdx.x >> 3;
    int rank = blockIdx.x & 7;
    int tid  = threadIdx.x;
    int lane = tid & 31;
    int y    = rank * 128 + (tid >> 2);
    int w0   = (tid & 3) * 8;
    uint32_t* B0 = &g_buf[0][img][0][0];
    uint32_t* B1 = &g_buf[1][img][0][0];
    int* flag = &g_flag[img * MAXIT];
    __shared__ int sflag;

    int cur = 0;  // t % 3, t = 2*iter + sub
    for (int iter = 0; iter < MAXIT; ++iter) {
        if (tid == 0) sflag = 0;
        __syncthreads();

        // ---- substep 0: B0 -> B1 ----
        {
            bool recompute = true;
            if (iter > 0) {
                int p1 = (cur + 2) % 3, p2 = (cur + 1) % 3;
                const uint8_t* r1 = &g_rowch[p1][img][0];
                const uint8_t* r2 = &g_rowch[p2][img][0];
                unsigned d = (unsigned)__ldcg(r1 + y) | (unsigned)__ldcg(r2 + y);
                if (y > 0)      d |= (unsigned)__ldcg(r1 + y - 1) | (unsigned)__ldcg(r2 + y - 1);
                if (y < HH - 1) d |= (unsigned)__ldcg(r1 + y + 1) | (unsigned)__ldcg(r2 + y + 1);
                recompute = (d != 0u);
            }
            uint32_t ch = 0;
            if (recompute) ch = thin_words<0>(B0, B1, y, w0);
            unsigned bal = __ballot_sync(0xffffffffu, ch != 0u);
            if ((tid & 3) == 0)
                g_rowch[cur][img][y] = (uint8_t)(((bal >> (lane & 28)) & 0xFu) ? 1 : 0);
            if (bal && lane == 0) sflag = 1;
        }
        __threadfence();
        cluster_sync_();                      // B1 + flags visible cluster-wide
        cur = (cur + 1) % 3;

        // ---- substep 1: B1 -> B0 ----
        {
            bool recompute = true;
            if (iter > 0) {
                int p1 = (cur + 2) % 3, p2 = (cur + 1) % 3;
                const uint8_t* r1 = &g_rowch[p1][img][0];
                const uint8_t* r2 = &g_rowch[p2][img][0];
                unsigned d = (unsigned)__ldcg(r1 + y) | (unsigned)__ldcg(r2 + y);
                if (y > 0)      d |= (unsigned)__ldcg(r1 + y - 1) | (unsigned)__ldcg(r2 + y - 1);
                if (y < HH - 1) d |= (unsigned)__ldcg(r1 + y + 1) | (unsigned)__ldcg(r2 + y + 1);
                recompute = (d != 0u);
            }
            uint32_t ch = 0;
            if (recompute) ch = thin_words<1>(B1, B0, y, w0);
            unsigned bal = __ballot_sync(0xffffffffu, ch != 0u);
            if ((tid & 3) == 0)
                g_rowch[cur][img][y] = (uint8_t)(((bal >> (lane & 28)) & 0xFu) ? 1 : 0);
            if (bal && lane == 0) sflag = 1;
        }
        __syncthreads();
        if (tid == 0 && sflag) atomicOr(&flag[iter], 1);
        __threadfence();
        cluster_sync_();                      // B0 + iteration flag visible
        cur = (cur + 1) % 3;
        if (__ldcg(&flag[iter]) == 0) break;  // uniform across the cluster
    }

    // ---- fused endpoint extraction: C = skeleton & (Bn == 1) ----
    endpoint_words(B0, img, y, w0);
}

// ---------------------------------------------------------------------------
// K3: fused 9x9 endpoint-density weight + BCE, block partial sums
//     (bit-plane vertical CSA + per-pixel 4-plane popc)
// ---------------------------------------------------------------------------
#define FA3(a, b, c, s, cy) { uint32_t _x = (a) ^ (b); (s) = _x ^ (c); (cy) = ((a) & (b)) | ((c) & _x); }

__global__ void __launch_bounds__(256) k_loss(const float* __restrict__ pred,
                                              const float* __restrict__ targ) {
    int idx = blockIdx.x * 256 + threadIdx.x;   // thread per 32-px word
    int w = idx & 31, y = (idx >> 5) & 1023, img = idx >> 15;
    const uint32_t* C = &g_cbits[img][0][0];

    uint32_t rlo[9], rhi[9], orAll = 0;
    #pragma unroll
    for (int d = 0; d < 9; ++d) {
        int r = y + d - 4;
        uint32_t L = 0, M = 0, R = 0;
        if (r >= 0 && r < HH) {
            M = C[r * WW + w];
            L = (w > 0) ? C[r * WW + w - 1] : 0u;
            R = (w < WW - 1) ? C[r * WW + w + 1] : 0u;
        }
        rlo[d] = (L >> 28) | (M << 4);            // 64-bit window, bit b = col b-4
        rhi[d] = (M >> 28) | ((R & 0xFu) << 4);
        orAll |= rlo[d] | rhi[d];
    }

    // vertical 9-row sum -> 4 bit planes (lo/hi halves)
    uint32_t S0l, S1l, S2l, S3l, S0h, S1h, S2h, S3h;
    {
        uint32_t s1, c1, s2, c2, s3, c3, c4, s5, c5, c6;
        FA3(rlo[0], rlo[1], rlo[2], s1, c1);
        FA3(rlo[3], rlo[4], rlo[5], s2, c2);
        FA3(rlo[6], rlo[7], rlo[8], s3, c3);
        FA3(s1, s2, s3, S0l, c4);
        FA3(c1, c2, c3, s5, c5);
        S1l = s5 ^ c4; c6 = s5 & c4;
        S2l = c5 ^ c6; S3l = c5 & c6;
        FA3(rhi[0], rhi[1], rhi[2], s1, c1);
        FA3(rhi[3], rhi[4], rhi[5], s2, c2);
        FA3(rhi[6], rhi[7], rhi[8], s3, c3);
        FA3(s1, s2, s3, S0h, c4);
        FA3(c1, c2, c3, s5, c5);
        S1h = s5 ^ c4; c6 = s5 & c4;
        S2h = c5 ^ c6; S3h = c5 & c6;
    }

    size_t poff = ((size_t)img * HH + y) * WPX + (size_t)w * 32;
    const float4* p4 = (const float4*)(pred + poff);
    const float4* t4 = (const float4*)(targ + poff);
    float fsum = 0.0f;
    #pragma unroll
    for (int q = 0; q < 8; ++q) {
        float4 pv = p4[q], tv = t4[q];
        float pa[4] = {pv.x, pv.y, pv.z, pv.w};
        float ta[4] = {tv.x, tv.y, tv.z, tv.w};
        #pragma unroll
        for (int j = 0; j < 4; ++j) {
            int k = q * 4 + j;
            float p = pa[j], t = ta[j];
            float Lb = -(t * __logf(p) + (1.0f - t) * __logf(1.0f - p));
            float Wt = 1.0f;
            if (orAll) {
                int nsum = __popc(__funnelshift_r(S0l, S0h, k) & 0x1FFu)
                         + (__popc(__funnelshift_r(S1l, S1h, k) & 0x1FFu) << 1)
                         + (__popc(__funnelshift_r(S2l, S2h, k) & 0x1FFu) << 2)
                         + (__popc(__funnelshift_r(S3l, S3h, k) & 0x1FFu) << 3);
                if (nsum) Wt = 60.0f * (float)nsum;
            }
            fsum += Wt * Lb;
        }
    }
    __shared__ double sd[256];
    sd[threadIdx.x] = (double)fsum;
    __syncthreads();
    #pragma unroll
    for (int s = 128; s > 0; s >>= 1) {
        if (threadIdx.x < s) sd[threadIdx.x] += sd[threadIdx.x + s];
        __syncthreads();
    }
    if (threadIdx.x == 0) g_partial[blockIdx.x] = sd[0];
}

// ---------------------------------------------------------------------------
// K4: deterministic final reduction -> mean (float)
// ---------------------------------------------------------------------------
__global__ void __launch_bounds__(1024) k_reduce(float* __restrict__ out) {
    __shared__ double sd[1024];
    int t = threadIdx.x;
    sd[t] = g_partial[t];
    __syncthreads();
    #pragma unroll
    for (int s = 512; s > 0; s >>= 1) {
        if (t < s) sd[t] += sd[t + s];
        __syncthreads();
    }
    if (t == 0) out[0] = (float)(sd[0] * (1.0 / ((double)IMGS * HH * WPX)));
}

// ---------------------------------------------------------------------------
extern "C" void kernel_launch(void* const* d_in, const int* in_sizes, int n_in,
                              void* d_out, int out_size) {
    (void)in_sizes; (void)n_in; (void)out_size;
    const float* pred = (const float*)d_in[0];
    const float* targ = (const float*)d_in[1];
    float* out = (float*)d_out;

    k_pack<<<1024, 256>>>(pred);
    k_thin<<<64, 512>>>();
    k_loss<<<1024, 256>>>(pred, targ);
    k_reduce<<<1, 1024>>>(out);
}

// round 3
// speedup vs baseline: 1.3290x; 1.0700x over previous
#include <cuda_runtime.h>
#include <cstdint>

#define IMGS 8
#define HH 1024
#define WPX 1024
#define WW 32            // 32-bit words per row
#define MAXIT 64

// Static scratch (no allocations allowed)
__device__ uint32_t g_buf[2][IMGS][HH][WW];   // ping-pong bitpacked images (2 MB)
__device__ uint32_t g_cbits[IMGS][HH][WW];    // endpoint bits (1 MB)
__device__ int      g_flag[IMGS * MAXIT];     // per-image per-iteration changed flags
__device__ uint8_t  g_rowch[3][IMGS][HH];     // rolling per-row change flags
__device__ double   g_partial[1024];          // block partial sums
__device__ int      g_count;                  // finished-block counter for k_loss

// ---------------------------------------------------------------------------
// helpers
// ---------------------------------------------------------------------------
__device__ __forceinline__ uint32_t shW(uint32_t l, uint32_t m) {
    return __funnelshift_l(l, m, 1);     // west neighbor mask
}
__device__ __forceinline__ uint32_t shE(uint32_t m, uint32_t r) {
    return __funnelshift_r(m, r, 1);     // east neighbor mask
}

struct Bn4 { uint32_t n0, n1, n2, n3; };  // bit-sliced neighbor count

__device__ __forceinline__ Bn4 bn8(uint32_t P2, uint32_t P3, uint32_t P4, uint32_t P5,
                                   uint32_t P6, uint32_t P7, uint32_t P8, uint32_t P9) {
    uint32_t s1 = P2 ^ P3 ^ P4, k1 = (P2 & P3) | (P4 & (P2 | P3));
    uint32_t s2 = P5 ^ P6 ^ P7, k2 = (P5 & P6) | (P7 & (P5 | P6));
    uint32_t s3 = s1 ^ s2 ^ P8, k3 = (s1 & s2) | (P8 & (s1 | s2));
    uint32_t n0 = s3 ^ P9,      k4 = s3 & P9;
    uint32_t s4 = k1 ^ k2 ^ k3, k5 = (k1 & k2) | (k3 & (k1 | k2));
    uint32_t n1 = s4 ^ k4,      k6 = s4 & k4;
    Bn4 r; r.n0 = n0; r.n1 = n1; r.n2 = k5 ^ k6; r.n3 = k5 & k6; return r;
}

// ---------------------------------------------------------------------------
// K1: threshold + bitpack pred>=0.5 into g_buf[0]; zero flags + counter
// ---------------------------------------------------------------------------
__global__ void __launch_bounds__(256) k_pack(const float* __restrict__ pred) {
    int warp = threadIdx.x >> 5, lane = threadIdx.x & 31;
    int ry = blockIdx.x * 8 + warp;            // global row 0..8191
    int img = ry >> 10, y = ry & 1023;
    const float* row = pred + (size_t)ry * WPX;
    #pragma unroll 4
    for (int w = 0; w < WW; ++w) {
        float p = row[w * 32 + lane];
        unsigned b = __ballot_sync(0xffffffffu, p >= 0.5f);
        if (lane == 0) g_buf[0][img][y][w] = b;
    }
    int z = blockIdx.x * 256 + threadIdx.x;
    if (z < IMGS * MAXIT) g_flag[z] = 0;
    if (z == IMGS * MAXIT) g_count = 0;
}

// ---------------------------------------------------------------------------
// K2: persistent cluster thinning with dirty-row skipping + fused endpoints.
//     Compiled for both 8-CTA (fallback) and 16-CTA (preferred) clusters.
// ---------------------------------------------------------------------------
__device__ __forceinline__ void cluster_sync_() {
    asm volatile("barrier.cluster.arrive.aligned;" ::: "memory");
    asm volatile("barrier.cluster.wait.aligned;" ::: "memory");
}

template <int SUB>
__device__ __forceinline__ uint32_t thin_words(const uint32_t* __restrict__ S,
                                               uint32_t* __restrict__ D,
                                               int y, int w0) {
    uint32_t a[10], c[10], b[10];
    const uint32_t* rc = S + y * WW;
    bool yt = (y == 0), yb = (y == HH - 1);
    #pragma unroll
    for (int i = 0; i < 10; ++i) {
        int w = w0 - 1 + i;
        bool ok = (w >= 0) && (w < WW);
        c[i] = ok ? rc[w] : 0u;
        a[i] = (ok && !yt) ? rc[w - WW] : 0u;
        b[i] = (ok && !yb) ? rc[w + WW] : 0u;
    }
    uint32_t ch = 0;
    #pragma unroll
    for (int i = 0; i < 8; ++i) {
        uint32_t aL = a[i], aM = a[i + 1], aR = a[i + 2];
        uint32_t cL = c[i], cM = c[i + 1], cR = c[i + 2];
        uint32_t bL = b[i], bM = b[i + 1], bR = b[i + 2];
        uint32_t P2 = aM, P6 = bM;
        uint32_t P3 = shE(aM, aR), P4 = shE(cM, cR), P5 = shE(bM, bR);
        uint32_t P7 = shW(bL, bM), P8 = shW(cL, cM), P9 = shW(aL, aM);
        Bn4 n = bn8(P2, P3, P4, P5, P6, P7, P8, P9);
        uint32_t ge2 = n.n1 | n.n2 | n.n3;
        uint32_t ge7 = n.n3 | (n.n0 & n.n1 & n.n2);
        uint32_t condB = ge2 & ~ge7;
        uint32_t t, acc, multi;
        acc = ~P2 & P3; multi = 0u;
        t = ~P3 & P4; multi |= acc & t; acc |= t;
        t = ~P4 & P5; multi |= acc & t; acc |= t;
        t = ~P5 & P6; multi |= acc & t; acc |= t;
        t = ~P6 & P7; multi |= acc & t; acc |= t;
        t = ~P7 & P8; multi |= acc & t; acc |= t;
        t = ~P8 & P9; multi |= acc & t; acc |= t;
        t = ~P9 & P2; multi |= acc & t; acc |= t;
        uint32_t A1 = acc & ~multi;
        uint32_t e1, e2;
        if (SUB == 0) { e1 = ~(P2 & P4 & P6); e2 = ~(P4 & P6 & P8); }
        else          { e1 = ~(P2 & P4 & P8); e2 = ~(P2 & P6 & P8); }
        uint32_t rem = cM & condB & A1 & e1 & e2;
        D[y * WW + w0 + i] = cM ^ rem;
        ch |= rem;
    }
    return ch;
}

__device__ __forceinline__ void endpoint_words(const uint32_t* __restrict__ S,
                                               int img, int y, int w0) {
    uint32_t a[10], c[10], b[10];
    const uint32_t* rc = S + y * WW;
    bool yt = (y == 0), yb = (y == HH - 1);
    #pragma unroll
    for (int i = 0; i < 10; ++i) {
        int w = w0 - 1 + i;
        bool ok = (w >= 0) && (w < WW);
        c[i] = ok ? rc[w] : 0u;
        a[i] = (ok && !yt) ? rc[w - WW] : 0u;
        b[i] = (ok && !yb) ? rc[w + WW] : 0u;
    }
    #pragma unroll
    for (int i = 0; i < 8; ++i) {
        uint32_t aL = a[i], aM = a[i + 1], aR = a[i + 2];
        uint32_t cL = c[i], cM = c[i + 1], cR = c[i + 2];
        uint32_t bL = b[i], bM = b[i + 1], bR = b[i + 2];
        uint32_t P2 = aM, P6 = bM;
        uint32_t P3 = shE(aM, aR), P4 = shE(cM, cR), P5 = shE(bM, bR);
        uint32_t P7 = shW(bL, bM), P8 = shW(cL, cM), P9 = shW(aL, aM);
        Bn4 n = bn8(P2, P3, P4, P5, P6, P7, P8, P9);
        g_cbits[img][y][w0 + i] = cM & n.n0 & ~(n.n1 | n.n2 | n.n3);
    }
}

__device__ __forceinline__ void thin_body(int img, int y, int tid) {
    int lane = tid & 31;
    int w0   = (tid & 3) * 8;
    uint32_t* B0 = &g_buf[0][img][0][0];
    uint32_t* B1 = &g_buf[1][img][0][0];
    int* flag = &g_flag[img * MAXIT];
    __shared__ int sflag;

    int cur = 0;
    for (int iter = 0; iter < MAXIT; ++iter) {
        if (tid == 0) sflag = 0;
        __syncthreads();

        // ---- substep 0: B0 -> B1 ----
        {
            bool recompute = true;
            if (iter > 0) {
                int p1 = (cur + 2) % 3, p2 = (cur + 1) % 3;
                const uint8_t* r1 = &g_rowch[p1][img][0];
                const uint8_t* r2 = &g_rowch[p2][img][0];
                unsigned d = (unsigned)__ldcg(r1 + y) | (unsigned)__ldcg(r2 + y);
                if (y > 0)      d |= (unsigned)__ldcg(r1 + y - 1) | (unsigned)__ldcg(r2 + y - 1);
                if (y < HH - 1) d |= (unsigned)__ldcg(r1 + y + 1) | (unsigned)__ldcg(r2 + y + 1);
                recompute = (d != 0u);
            }
            uint32_t ch = 0;
            if (recompute) ch = thin_words<0>(B0, B1, y, w0);
            unsigned bal = __ballot_sync(0xffffffffu, ch != 0u);
            if ((tid & 3) == 0)
                g_rowch[cur][img][y] = (uint8_t)(((bal >> (lane & 28)) & 0xFu) ? 1 : 0);
            if (bal && lane == 0) sflag = 1;
        }
        __threadfence();
        cluster_sync_();
        cur = (cur + 1) % 3;

        // ---- substep 1: B1 -> B0 ----
        {
            bool recompute = true;
            if (iter > 0) {
                int p1 = (cur + 2) % 3, p2 = (cur + 1) % 3;
                const uint8_t* r1 = &g_rowch[p1][img][0];
                const uint8_t* r2 = &g_rowch[p2][img][0];
                unsigned d = (unsigned)__ldcg(r1 + y) | (unsigned)__ldcg(r2 + y);
                if (y > 0)      d |= (unsigned)__ldcg(r1 + y - 1) | (unsigned)__ldcg(r2 + y - 1);
                if (y < HH - 1) d |= (unsigned)__ldcg(r1 + y + 1) | (unsigned)__ldcg(r2 + y + 1);
                recompute = (d != 0u);
            }
            uint32_t ch = 0;
            if (recompute) ch = thin_words<1>(B1, B0, y, w0);
            unsigned bal = __ballot_sync(0xffffffffu, ch != 0u);
            if ((tid & 3) == 0)
                g_rowch[cur][img][y] = (uint8_t)(((bal >> (lane & 28)) & 0xFu) ? 1 : 0);
            if (bal && lane == 0) sflag = 1;
        }
        __syncthreads();
        if (tid == 0 && sflag) atomicOr(&flag[iter], 1);
        __threadfence();
        cluster_sync_();
        cur = (cur + 1) % 3;
        if (__ldcg(&flag[iter]) == 0) break;
    }

    endpoint_words(B0, img, y, tid & 3 ? w0 : w0);  // keep w0
}

__global__ void __cluster_dims__(16, 1, 1) __launch_bounds__(256, 1) k_thin16() {
    int img  = blockIdx.x >> 4;
    int rank = blockIdx.x & 15;
    int tid  = threadIdx.x;
    int y    = rank * 64 + (tid >> 2);
    thin_body(img, y, tid);
}

__global__ void __cluster_dims__(8, 1, 1) __launch_bounds__(512, 1) k_thin8() {
    int img  = blockIdx.x >> 3;
    int rank = blockIdx.x & 7;
    int tid  = threadIdx.x;
    int y    = rank * 128 + (tid >> 2);
    thin_body(img, y, tid);
}

// ---------------------------------------------------------------------------
// K3: fused 9x9 endpoint-density weight + BCE + FULL deterministic reduction
// ---------------------------------------------------------------------------
#define FA3(a, b, c, s, cy) { uint32_t _x = (a) ^ (b); (s) = _x ^ (c); (cy) = ((a) & (b)) | ((c) & _x); }

__global__ void __launch_bounds__(256) k_loss(const float* __restrict__ pred,
                                              const float* __restrict__ targ,
                                              float* __restrict__ out) {
    int idx = blockIdx.x * 256 + threadIdx.x;   // thread per 32-px word
    int w = idx & 31, y = (idx >> 5) & 1023, img = idx >> 15;
    const uint32_t* C = &g_cbits[img][0][0];

    uint32_t rlo[9], rhi[9], orAll = 0;
    #pragma unroll
    for (int d = 0; d < 9; ++d) {
        int r = y + d - 4;
        uint32_t L = 0, M = 0, R = 0;
        if (r >= 0 && r < HH) {
            M = C[r * WW + w];
            L = (w > 0) ? C[r * WW + w - 1] : 0u;
            R = (w < WW - 1) ? C[r * WW + w + 1] : 0u;
        }
        rlo[d] = (L >> 28) | (M << 4);            // 64-bit window, bit b = col b-4
        rhi[d] = (M >> 28) | ((R & 0xFu) << 4);
        orAll |= rlo[d] | rhi[d];
    }

    // vertical 9-row sum -> 4 bit planes (lo/hi halves)
    uint32_t S0l, S1l, S2l, S3l, S0h, S1h, S2h, S3h;
    {
        uint32_t s1, c1, s2, c2, s3, c3, c4, s5, c5, c6;
        FA3(rlo[0], rlo[1], rlo[2], s1, c1);
        FA3(rlo[3], rlo[4], rlo[5], s2, c2);
        FA3(rlo[6], rlo[7], rlo[8], s3, c3);
        FA3(s1, s2, s3, S0l, c4);
        FA3(c1, c2, c3, s5, c5);
        S1l = s5 ^ c4; c6 = s5 & c4;
        S2l = c5 ^ c6; S3l = c5 & c6;
        FA3(rhi[0], rhi[1], rhi[2], s1, c1);
        FA3(rhi[3], rhi[4], rhi[5], s2, c2);
        FA3(rhi[6], rhi[7], rhi[8], s3, c3);
        FA3(s1, s2, s3, S0h, c4);
        FA3(c1, c2, c3, s5, c5);
        S1h = s5 ^ c4; c6 = s5 & c4;
        S2h = c5 ^ c6; S3h = c5 & c6;
    }

    size_t poff = ((size_t)img * HH + y) * WPX + (size_t)w * 32;
    const float4* p4 = (const float4*)(pred + poff);
    const float4* t4 = (const float4*)(targ + poff);
    float fsum = 0.0f;
    #pragma unroll
    for (int q = 0; q < 8; ++q) {
        float4 pv = p4[q], tv = t4[q];
        float pa[4] = {pv.x, pv.y, pv.z, pv.w};
        float ta[4] = {tv.x, tv.y, tv.z, tv.w};
        #pragma unroll
        for (int j = 0; j < 4; ++j) {
            int k = q * 4 + j;
            float p = pa[j], t = ta[j];
            float Lb = -(t * __logf(p) + (1.0f - t) * __logf(1.0f - p));
            float Wt = 1.0f;
            if (orAll) {
                int nsum = __popc(__funnelshift_r(S0l, S0h, k) & 0x1FFu)
                         + (__popc(__funnelshift_r(S1l, S1h, k) & 0x1FFu) << 1)
                         + (__popc(__funnelshift_r(S2l, S2h, k) & 0x1FFu) << 2)
                         + (__popc(__funnelshift_r(S3l, S3h, k) & 0x1FFu) << 3);
                if (nsum) Wt = 60.0f * (float)nsum;
            }
            fsum += Wt * Lb;
        }
    }
    __shared__ double sd[256];
    sd[threadIdx.x] = (double)fsum;
    __syncthreads();
    #pragma unroll
    for (int s = 128; s > 0; s >>= 1) {
        if (threadIdx.x < s) sd[threadIdx.x] += sd[threadIdx.x + s];
        __syncthreads();
    }
    __shared__ int slast;
    if (threadIdx.x == 0) {
        g_partial[blockIdx.x] = sd[0];
        __threadfence();
        slast = (atomicAdd(&g_count, 1) == gridDim.x - 1);
    }
    __syncthreads();
    if (!slast) return;

    // last block: deterministic fixed-order final reduction of 1024 partials
    int t = threadIdx.x;
    double v = __ldcg(&g_partial[t]) + __ldcg(&g_partial[t + 256])
             + __ldcg(&g_partial[t + 512]) + __ldcg(&g_partial[t + 768]);
    sd[t] = v;
    __syncthreads();
    #pragma unroll
    for (int s = 128; s > 0; s >>= 1) {
        if (t < s) sd[t] += sd[t + s];
        __syncthreads();
    }
    if (t == 0) out[0] = (float)(sd[0] * (1.0 / ((double)IMGS * HH * WPX)));
}

// ---------------------------------------------------------------------------
extern "C" void kernel_launch(void* const* d_in, const int* in_sizes, int n_in,
                              void* d_out, int out_size) {
    (void)in_sizes; (void)n_in; (void)out_size;
    const float* pred = (const float*)d_in[0];
    const float* targ = (const float*)d_in[1];
    float* out = (float*)d_out;

    k_pack<<<1024, 256>>>(pred);

    cudaError_t e = cudaFuncSetAttribute(
        (const void*)k_thin16, cudaFuncAttributeNonPortableClusterSizeAllowed, 1);
    if (e == cudaSuccess) {
        k_thin16<<<128, 256>>>();
    } else {
        (void)cudaGetLastError();   // clear sticky error before capture continues
        k_thin8<<<64, 512>>>();
    }

    k_loss<<<1024, 256>>>(pred, targ, out);
}

// round 5
// speedup vs baseline: 1.6991x; 1.2785x over previous
#include <cuda_runtime.h>
#include <cooperative_groups.h>
#include <cstdint>

namespace cg = cooperative_groups;

#define IMGS 8
#define HH 1024
#define WPX 1024
#define WW 32            // 32-bit words per row
#define WP 33            // padded row stride (bank-conflict-free)
#define MAXIT 64

// Static global scratch (no allocations allowed)
__device__ uint32_t g_cbits[IMGS][HH][WW];    // endpoint bits (1 MB)
__device__ int      g_flag[IMGS * MAXIT];     // per-image per-iteration changed flags
__device__ double   g_partial[1024];          // block partial sums
__device__ int      g_count;                  // finished-block counter for k_loss

// ---------------------------------------------------------------------------
// helpers
// ---------------------------------------------------------------------------
__device__ __forceinline__ uint32_t shW(uint32_t l, uint32_t m) {
    return __funnelshift_l(l, m, 1);     // west neighbor mask
}
__device__ __forceinline__ uint32_t shE(uint32_t m, uint32_t r) {
    return __funnelshift_r(m, r, 1);     // east neighbor mask
}

struct Bn4 { uint32_t n0, n1, n2, n3; };

__device__ __forceinline__ Bn4 bn8(uint32_t P2, uint32_t P3, uint32_t P4, uint32_t P5,
                                   uint32_t P6, uint32_t P7, uint32_t P8, uint32_t P9) {
    uint32_t s1 = P2 ^ P3 ^ P4, k1 = (P2 & P3) | (P4 & (P2 | P3));
    uint32_t s2 = P5 ^ P6 ^ P7, k2 = (P5 & P6) | (P7 & (P5 | P6));
    uint32_t s3 = s1 ^ s2 ^ P8, k3 = (s1 & s2) | (P8 & (s1 | s2));
    uint32_t n0 = s3 ^ P9,      k4 = s3 & P9;
    uint32_t s4 = k1 ^ k2 ^ k3, k5 = (k1 & k2) | (k3 & (k1 | k2));
    uint32_t n1 = s4 ^ k4,      k6 = s4 & k4;
    Bn4 r; r.n0 = n0; r.n1 = n1; r.n2 = k5 ^ k6; r.n3 = k5 & k6; return r;
}

template <int SUB>
__device__ __forceinline__ uint32_t thin_rows(const uint32_t* __restrict__ rowA,
                                              const uint32_t* __restrict__ rowC,
                                              const uint32_t* __restrict__ rowB,
                                              uint32_t* __restrict__ dst, int w0) {
    uint32_t a[10], c[10], b[10];
    #pragma unroll
    for (int i = 0; i < 10; ++i) {
        int w = w0 - 1 + i;
        bool ok = (w >= 0) && (w < WW);
        a[i] = ok ? rowA[w] : 0u;
        c[i] = ok ? rowC[w] : 0u;
        b[i] = ok ? rowB[w] : 0u;
    }
    uint32_t ch = 0;
    #pragma unroll
    for (int i = 0; i < 8; ++i) {
        uint32_t aL = a[i], aM = a[i + 1], aR = a[i + 2];
        uint32_t cL = c[i], cM = c[i + 1], cR = c[i + 2];
        uint32_t bL = b[i], bM = b[i + 1], bR = b[i + 2];
        uint32_t P2 = aM, P6 = bM;
        uint32_t P3 = shE(aM, aR), P4 = shE(cM, cR), P5 = shE(bM, bR);
        uint32_t P7 = shW(bL, bM), P8 = shW(cL, cM), P9 = shW(aL, aM);
        Bn4 n = bn8(P2, P3, P4, P5, P6, P7, P8, P9);
        uint32_t ge2 = n.n1 | n.n2 | n.n3;
        uint32_t ge7 = n.n3 | (n.n0 & n.n1 & n.n2);
        uint32_t condB = ge2 & ~ge7;
        uint32_t t, acc, multi;
        acc = ~P2 & P3; multi = 0u;
        t = ~P3 & P4; multi |= acc & t; acc |= t;
        t = ~P4 & P5; multi |= acc & t; acc |= t;
        t = ~P5 & P6; multi |= acc & t; acc |= t;
        t = ~P6 & P7; multi |= acc & t; acc |= t;
        t = ~P7 & P8; multi |= acc & t; acc |= t;
        t = ~P8 & P9; multi |= acc & t; acc |= t;
        t = ~P9 & P2; multi |= acc & t; acc |= t;
        uint32_t A1 = acc & ~multi;
        uint32_t e1, e2;
        if (SUB == 0) { e1 = ~(P2 & P4 & P6); e2 = ~(P4 & P6 & P8); }
        else          { e1 = ~(P2 & P4 & P8); e2 = ~(P2 & P6 & P8); }
        uint32_t rem = cM & condB & A1 & e1 & e2;
        dst[w0 + i] = cM ^ rem;
        ch |= rem;
    }
    return ch;
}

__device__ __forceinline__ void endpoint_rows(const uint32_t* __restrict__ rowA,
                                              const uint32_t* __restrict__ rowC,
                                              const uint32_t* __restrict__ rowB,
                                              int img, int gy, int w0) {
    uint32_t a[10], c[10], b[10];
    #pragma unroll
    for (int i = 0; i < 10; ++i) {
        int w = w0 - 1 + i;
        bool ok = (w >= 0) && (w < WW);
        a[i] = ok ? rowA[w] : 0u;
        c[i] = ok ? rowC[w] : 0u;
        b[i] = ok ? rowB[w] : 0u;
    }
    #pragma unroll
    for (int i = 0; i < 8; ++i) {
        uint32_t aL = a[i], aM = a[i + 1], aR = a[i + 2];
        uint32_t cL = c[i], cM = c[i + 1], cR = c[i + 2];
        uint32_t bL = b[i], bM = b[i + 1], bR = b[i + 2];
        uint32_t P2 = aM, P6 = bM;
        uint32_t P3 = shE(aM, aR), P4 = shE(cM, cR), P5 = shE(bM, bR);
        uint32_t P7 = shW(bL, bM), P8 = shW(cL, cM), P9 = shW(aL, aM);
        Bn4 n = bn8(P2, P3, P4, P5, P6, P7, P8, P9);
        g_cbits[img][gy][w0 + i] = cM & n.n0 & ~(n.n1 | n.n2 | n.n3);
    }
}

// ---------------------------------------------------------------------------
// Fused pack + SMEM-resident cluster thinning + endpoint extraction.
// Convergence flags live in GLOBAL memory (proven pattern from round 3):
// per-CTA atomicOr into g_flag[img*MAXIT+iter], read back after cluster.sync.
// ---------------------------------------------------------------------------
template <int ROWS>
struct ThinSmem {
    uint32_t img[2][ROWS][WP];   // ping-pong tiles, padded stride
    uint32_t zero[WP];
    uint8_t  rowch[3][ROWS];     // rolling per-row change flags
    int      sflag;
};

template <int NC, int ROWS, int NTHR, typename SM>
__device__ void thin_main(SM* sm, const float* __restrict__ pred) {
    cg::cluster_group cluster = cg::this_cluster();
    const int tid  = threadIdx.x;
    const int lane = tid & 31;
    const int warp = tid >> 5;
    const int rank = (int)cluster.block_rank();
    const int img  = blockIdx.x / NC;
    int* flag = &g_flag[img * MAXIT];

    // ---- pack phase: threshold pred into sm->img[0] (float4 + shfl-OR) ----
    constexpr int NWARP = NTHR / 32;
    for (int r = warp; r < ROWS; r += NWARP) {
        const float4* row = (const float4*)(pred + ((size_t)img * HH + (size_t)rank * ROWS + r) * WPX);
        #pragma unroll
        for (int step = 0; step < 8; ++step) {
            float4 v = row[step * 32 + lane];
            uint32_t nib = (v.x >= 0.5f ? 1u : 0u) | (v.y >= 0.5f ? 2u : 0u)
                         | (v.z >= 0.5f ? 4u : 0u) | (v.w >= 0.5f ? 8u : 0u);
            uint32_t x = nib << (4 * (lane & 7));
            x |= __shfl_xor_sync(0xffffffffu, x, 1);
            x |= __shfl_xor_sync(0xffffffffu, x, 2);
            x |= __shfl_xor_sync(0xffffffffu, x, 4);
            if ((lane & 7) == 0) sm->img[0][r][step * 4 + (lane >> 3)] = x;
        }
    }
    if (tid < WP) sm->zero[tid] = 0u;
    if (rank == 0) { for (int i = tid; i < MAXIT; i += NTHR) flag[i] = 0; }
    if (blockIdx.x == 0 && tid == 0) g_count = 0;
    __threadfence();
    cluster.sync();

    // peer tiles for halo access (plain DSMEM loads only)
    SM* pprev = (rank > 0)      ? (SM*)cluster.map_shared_rank(sm, rank - 1) : nullptr;
    SM* pnext = (rank < NC - 1) ? (SM*)cluster.map_shared_rank(sm, rank + 1) : nullptr;

    const int ly = tid >> 2;          // local row 0..ROWS-1
    const int w0 = (tid & 3) * 8;     // word group

    int cur = 0;  // rolling index into rowch, advanced each substep
    for (int iter = 0; iter < MAXIT; ++iter) {
        if (tid == 0) sm->sflag = 0;
        __syncthreads();

        // ---- substep 0: img[0] -> img[1] ----
        {
            bool recompute = true;
            if (iter > 0) {
                int p1 = (cur + 2) % 3, p2 = (cur + 1) % 3;
                unsigned d = (unsigned)sm->rowch[p1][ly] | (unsigned)sm->rowch[p2][ly];
                if (ly > 0)        d |= (unsigned)sm->rowch[p1][ly - 1] | (unsigned)sm->rowch[p2][ly - 1];
                else if (pprev)    d |= (unsigned)pprev->rowch[p1][ROWS - 1] | (unsigned)pprev->rowch[p2][ROWS - 1];
                if (ly < ROWS - 1) d |= (unsigned)sm->rowch[p1][ly + 1] | (unsigned)sm->rowch[p2][ly + 1];
                else if (pnext)    d |= (unsigned)pnext->rowch[p1][0] | (unsigned)pnext->rowch[p2][0];
                recompute = (d != 0u);
            }
            uint32_t ch = 0;
            if (recompute) {
                const uint32_t* rA = (ly > 0) ? sm->img[0][ly - 1]
                                  : (pprev ? pprev->img[0][ROWS - 1] : sm->zero);
                const uint32_t* rB = (ly < ROWS - 1) ? sm->img[0][ly + 1]
                                  : (pnext ? pnext->img[0][0] : sm->zero);
                ch = thin_rows<0>(rA, sm->img[0][ly], rB, sm->img[1][ly], w0);
            }
            unsigned bal = __ballot_sync(0xffffffffu, ch != 0u);
            if ((tid & 3) == 0)
                sm->rowch[cur][ly] = (uint8_t)(((bal >> (lane & 28)) & 0xFu) ? 1 : 0);
            if (bal && lane == 0) sm->sflag = 1;
        }
        cluster.sync();
        cur = (cur + 1) % 3;

        // ---- substep 1: img[1] -> img[0] ----
        {
            bool recompute = true;
            if (iter > 0) {
                int p1 = (cur + 2) % 3, p2 = (cur + 1) % 3;
                unsigned d = (unsigned)sm->rowch[p1][ly] | (unsigned)sm->rowch[p2][ly];
                if (ly > 0)        d |= (unsigned)sm->rowch[p1][ly - 1] | (unsigned)sm->rowch[p2][ly - 1];
                else if (pprev)    d |= (unsigned)pprev->rowch[p1][ROWS - 1] | (unsigned)pprev->rowch[p2][ROWS - 1];
                if (ly < ROWS - 1) d |= (unsigned)sm->rowch[p1][ly + 1] | (unsigned)sm->rowch[p2][ly + 1];
                else if (pnext)    d |= (unsigned)pnext->rowch[p1][0] | (unsigned)pnext->rowch[p2][0];
                recompute = (d != 0u);
            }
            uint32_t ch = 0;
            if (recompute) {
                const uint32_t* rA = (ly > 0) ? sm->img[1][ly - 1]
                                  : (pprev ? pprev->img[1][ROWS - 1] : sm->zero);
                const uint32_t* rB = (ly < ROWS - 1) ? sm->img[1][ly + 1]
                                  : (pnext ? pnext->img[1][0] : sm->zero);
                ch = thin_rows<1>(rA, sm->img[1][ly], rB, sm->img[0][ly], w0);
            }
            unsigned bal = __ballot_sync(0xffffffffu, ch != 0u);
            if ((tid & 3) == 0)
                sm->rowch[cur][ly] = (uint8_t)(((bal >> (lane & 28)) & 0xFu) ? 1 : 0);
            if (bal && lane == 0) sm->sflag = 1;
        }
        __syncthreads();
        if (tid == 0 && sm->sflag) { atomicOr(&flag[iter], 1); __threadfence(); }
        cluster.sync();
        cur = (cur + 1) % 3;
        if (__ldcg(&flag[iter]) == 0) break;   // uniform across the cluster
    }

    // ---- fused endpoint extraction from img[0] ----
    {
        const uint32_t* rA = (ly > 0) ? sm->img[0][ly - 1]
                          : (pprev ? pprev->img[0][ROWS - 1] : sm->zero);
        const uint32_t* rB = (ly < ROWS - 1) ? sm->img[0][ly + 1]
                          : (pnext ? pnext->img[0][0] : sm->zero);
        endpoint_rows(rA, sm->img[0][ly], rB, img, rank * ROWS + ly, w0);
    }
    cluster.sync();   // no CTA exits while peers may still read its smem
}

__global__ void __cluster_dims__(16, 1, 1) __launch_bounds__(256, 1)
k_thin16(const float* __restrict__ pred) {
    __shared__ ThinSmem<64> sm;
    thin_main<16, 64, 256>(&sm, pred);
}

__global__ void __cluster_dims__(8, 1, 1) __launch_bounds__(512, 1)
k_thin8(const float* __restrict__ pred) {
    __shared__ ThinSmem<128> sm;
    thin_main<8, 128, 512>(&sm, pred);
}

// ---------------------------------------------------------------------------
// K2: fused 9x9 endpoint-density weight + BCE + full deterministic reduction
// ---------------------------------------------------------------------------
#define FA3(a, b, c, s, cy) { uint32_t _x = (a) ^ (b); (s) = _x ^ (c); (cy) = ((a) & (b)) | ((c) & _x); }

__global__ void __launch_bounds__(256) k_loss(const float* __restrict__ pred,
                                              const float* __restrict__ targ,
                                              float* __restrict__ out) {
    int idx = blockIdx.x * 256 + threadIdx.x;   // thread per 32-px word
    int w = idx & 31, y = (idx >> 5) & 1023, img = idx >> 15;
    const uint32_t* C = &g_cbits[img][0][0];

    uint32_t rlo[9], rhi[9], orAll = 0;
    #pragma unroll
    for (int d = 0; d < 9; ++d) {
        int r = y + d - 4;
        uint32_t L = 0, M = 0, R = 0;
        if (r >= 0 && r < HH) {
            M = C[r * WW + w];
            L = (w > 0) ? C[r * WW + w - 1] : 0u;
            R = (w < WW - 1) ? C[r * WW + w + 1] : 0u;
        }
        rlo[d] = (L >> 28) | (M << 4);
        rhi[d] = (M >> 28) | ((R & 0xFu) << 4);
        orAll |= rlo[d] | rhi[d];
    }

    uint32_t S0l, S1l, S2l, S3l, S0h, S1h, S2h, S3h;
    {
        uint32_t s1, c1, s2, c2, s3, c3, c4, s5, c5, c6;
        FA3(rlo[0], rlo[1], rlo[2], s1, c1);
        FA3(rlo[3], rlo[4], rlo[5], s2, c2);
        FA3(rlo[6], rlo[7], rlo[8], s3, c3);
        FA3(s1, s2, s3, S0l, c4);
        FA3(c1, c2, c3, s5, c5);
        S1l = s5 ^ c4; c6 = s5 & c4;
        S2l = c5 ^ c6; S3l = c5 & c6;
        FA3(rhi[0], rhi[1], rhi[2], s1, c1);
        FA3(rhi[3], rhi[4], rhi[5], s2, c2);
        FA3(rhi[6], rhi[7], rhi[8], s3, c3);
        FA3(s1, s2, s3, S0h, c4);
        FA3(c1, c2, c3, s5, c5);
        S1h = s5 ^ c4; c6 = s5 & c4;
        S2h = c5 ^ c6; S3h = c5 & c6;
    }

    size_t poff = ((size_t)img * HH + y) * WPX + (size_t)w * 32;
    const float4* p4 = (const float4*)(pred + poff);
    const float4* t4 = (const float4*)(targ + poff);
    float fsum = 0.0f;
    #pragma unroll
    for (int q = 0; q < 8; ++q) {
        float4 pv = p4[q], tv = t4[q];
        float pa[4] = {pv.x, pv.y, pv.z, pv.w};
        float ta[4] = {tv.x, tv.y, tv.z, tv.w};
        #pragma unroll
        for (int j = 0; j < 4; ++j) {
            int k = q * 4 + j;
            float p = pa[j], t = ta[j];
            float Lb = -(t * __logf(p) + (1.0f - t) * __logf(1.0f - p));
            float Wt = 1.0f;
            if (orAll) {
                int nsum = __popc(__funnelshift_r(S0l, S0h, k) & 0x1FFu)
                         + (__popc(__funnelshift_r(S1l, S1h, k) & 0x1FFu) << 1)
                         + (__popc(__funnelshift_r(S2l, S2h, k) & 0x1FFu) << 2)
                         + (__popc(__funnelshift_r(S3l, S3h, k) & 0x1FFu) << 3);
                if (nsum) Wt = 60.0f * (float)nsum;
            }
            fsum += Wt * Lb;
        }
    }
    __shared__ double sd[256];
    sd[threadIdx.x] = (double)fsum;
    __syncthreads();
    #pragma unroll
    for (int s = 128; s > 0; s >>= 1) {
        if (threadIdx.x < s) sd[threadIdx.x] += sd[threadIdx.x + s];
        __syncthreads();
    }
    __shared__ int slast;
    if (threadIdx.x == 0) {
        g_partial[blockIdx.x] = sd[0];
        __threadfence();
        slast = (atomicAdd(&g_count, 1) == gridDim.x - 1);
    }
    __syncthreads();
    if (!slast) return;

    int t = threadIdx.x;
    double v = __ldcg(&g_partial[t]) + __ldcg(&g_partial[t + 256])
             + __ldcg(&g_partial[t + 512]) + __ldcg(&g_partial[t + 768]);
    sd[t] = v;
    __syncthreads();
    #pragma unroll
    for (int s = 128; s > 0; s >>= 1) {
        if (t < s) sd[t] += sd[t + s];
        __syncthreads();
    }
    if (t == 0) out[0] = (float)(sd[0] * (1.0 / ((double)IMGS * HH * WPX)));
}

// ---------------------------------------------------------------------------
extern "C" void kernel_launch(void* const* d_in, const int* in_sizes, int n_in,
                              void* d_out, int out_size) {
    (void)in_sizes; (void)n_in; (void)out_size;
    const float* pred = (const float*)d_in[0];
    const float* targ = (const float*)d_in[1];
    float* out = (float*)d_out;

    cudaError_t e = cudaFuncSetAttribute(
        (const void*)k_thin16, cudaFuncAttributeNonPortableClusterSizeAllowed, 1);
    if (e == cudaSuccess) {
        k_thin16<<<128, 256>>>(pred);
    } else {
        (void)cudaGetLastError();   // clear sticky error before capture continues
        k_thin8<<<64, 512>>>(pred);
    }

    k_loss<<<1024, 256>>>(pred, targ, out);
}